// round 7
// baseline (speedup 1.0000x reference)
#include <cuda_runtime.h>
#include <cuda_bf16.h>
#include <cuda_fp16.h>
#include <cstdint>

#define B_   8
#define C_   64
#define N_   4096
#define K_   20
#define M_   8
#define OUTC 64
#define CM   512   // C_*M_
#define NEG_SLOPE 0.2f

// Scratch (device globals; no dynamic allocation allowed)
__device__ float           g_ft[B_ * N_ * C_];                    // feature (B,N,C)   : 8 MB
__device__ float           g_xt[B_ * N_ * 4];                     // x (B,N,4) padded  : 512 KB
__device__ __nv_bfloat16   g_agg_hi[(size_t)B_ * N_ * CM];       // agg hi            : 32 MB
__device__ __nv_bfloat16   g_agg_lo[(size_t)B_ * N_ * CM];       // agg lo            : 32 MB
__device__ __nv_bfloat16   g_w_hi[OUTC * CM];                    // W hi              : 64 KB
__device__ __nv_bfloat16   g_w_lo[OUTC * CM];                    // W lo              : 64 KB
__device__ int             g_idx_is64;

// packed f32x2 helpers (sm_100+; ptxas never emits FFMA2 from C++)
#define FMA2(d, a, b) \
    asm volatile("fma.rn.f32x2 %0, %1, %2, %0;" : "+l"(d) : "l"(a), "l"(b))
#define PACK_BCAST(dst, v) do { unsigned r_ = __float_as_uint(v); \
    asm("mov.b64 %0, {%1,%2};" : "=l"(dst) : "r"(r_), "r"(r_)); } while (0)
#define PACKF2(dst, lo, hi) do { unsigned lo_ = __float_as_uint(lo), hi_ = __float_as_uint(hi); \
    asm("mov.b64 %0, {%1,%2};" : "=l"(dst) : "r"(lo_), "r"(hi_)); } while (0)
#define UNPACK2(lo, hi, v) do { unsigned lo_, hi_; \
    asm("mov.b64 {%0,%1}, %2;" : "=r"(lo_), "=r"(hi_) : "l"(v)); \
    lo = __uint_as_float(lo_); hi = __uint_as_float(hi_); } while (0)

// ----------------------------------------------------------------------------
// Kernel 0: detect index dtype (int64 vs int32)
// ----------------------------------------------------------------------------
__global__ void detect_kernel(const int* __restrict__ raw) {
    int all0 = 1;
#pragma unroll
    for (int j = 1; j < 64; j += 2)
        if (raw[j] != 0) all0 = 0;
    g_idx_is64 = all0;
}

// ----------------------------------------------------------------------------
// Kernel 0b: split conv_w into bf16 hi/lo
// ----------------------------------------------------------------------------
__global__ void convw_kernel(const float* __restrict__ W) {
    int i = blockIdx.x * 256 + threadIdx.x;
    float w = W[i];
    __nv_bfloat16 h = __float2bfloat16(w);
    g_w_hi[i] = h;
    g_w_lo[i] = __float2bfloat16(w - __bfloat162float(h));
}

// ----------------------------------------------------------------------------
// Kernel 0c: transpose x (B,3,N) -> g_xt (B,N,4)
// ----------------------------------------------------------------------------
__global__ void transpose_x_kernel(const float* __restrict__ x) {
    int b = blockIdx.y;
    int n = blockIdx.x * 256 + threadIdx.x;
    const float* xb = x + (size_t)b * 3 * N_;
    float4 v = make_float4(xb[n], xb[N_ + n], xb[2 * N_ + n], 0.0f);
    *(float4*)&g_xt[((size_t)b * N_ + n) * 4] = v;
}

// ----------------------------------------------------------------------------
// Kernel 1: transpose feature (B,C,N) -> g_ft (B,N,C)
// ----------------------------------------------------------------------------
__global__ void transpose_kernel(const float* __restrict__ feature) {
    __shared__ float tile[32][33];
    int b  = blockIdx.z;
    int n0 = blockIdx.x * 32;
    int c0 = blockIdx.y * 32;
    int tx = threadIdx.x, ty = threadIdx.y;
#pragma unroll
    for (int i = 0; i < 4; i++) {
        int c = c0 + ty + i * 8;
        tile[ty + i * 8][tx] = feature[((size_t)b * C_ + c) * N_ + n0 + tx];
    }
    __syncthreads();
#pragma unroll
    for (int i = 0; i < 4; i++) {
        int n = n0 + ty + i * 8;
        g_ft[((size_t)b * N_ + n) * C_ + c0 + tx] = tile[tx][ty + i * 8];
    }
}

// ----------------------------------------------------------------------------
// Kernel 2: per-point perm + softmax + agg -> bf16 hi/lo
// 256 threads, 8 points/CTA, 32 threads/point. P in fp16 (single LDS.128/k),
// math in fp32 FFMA2, gather MLP=4.
// ----------------------------------------------------------------------------
__global__ void __launch_bounds__(256)
agg_kernel(const void* __restrict__ nidx,
           const float* __restrict__ kern) {
    __shared__ __align__(16) int    sIdx[8][K_];
    __shared__ __align__(16) float  sP[8][K_][M_];
    __shared__ __align__(16) __half sPh[8][K_][M_];

    int t  = threadIdx.x;
    int q0 = blockIdx.x * 8;
    int is64 = g_idx_is64;

    // phase 1 (160 threads): idx load + x gather (float4) + perm row
    if (t < 8 * K_) {
        int g = t / K_, k = t % K_;
        int q = q0 + g;
        int b = q >> 12;
        size_t pos = (size_t)q * K_ + k;
        int i, i0;
        if (is64) {
            i  = (int)((const long long*)nidx)[pos];
            i0 = (int)((const long long*)nidx)[(size_t)q * K_];
        } else {
            i  = ((const int*)nidx)[pos];
            i0 = ((const int*)nidx)[(size_t)q * K_];
        }
        i  &= (N_ - 1);      // safety clamp (no-op for valid indices)
        i0 &= (N_ - 1);
        sIdx[g][k] = i;
        float4 xv  = *(const float4*)&g_xt[((size_t)b * N_ + i) * 4];
        float4 x0v = *(const float4*)&g_xt[((size_t)b * N_ + i0) * 4];
        float x0 = xv.x - x0v.x;
        float x1 = xv.y - x0v.y;
        float x2 = xv.z - x0v.z;
#pragma unroll
        for (int m = 0; m < M_; m++) {
            float v = x0 * kern[m] + x1 * kern[M_ + m] + x2 * kern[2 * M_ + m];
            if (k == 0 && m == 0) v += 1.0f;
            sP[g][k][m] = v;
        }
    }
    __syncthreads();

    // phase 2 (64 threads): softmax over k per (point, m) -> fp16 sPh
    if (t < 8 * M_) {
        int g = t >> 3, m = t & 7;
        float e[K_];
        float mx = -1e30f;
#pragma unroll
        for (int k = 0; k < K_; k++) mx = fmaxf(mx, sP[g][k][m]);
        float s = 0.0f;
#pragma unroll
        for (int k = 0; k < K_; k++) {
            float ee = __expf(sP[g][k][m] - mx);
            e[k] = ee;
            s += ee;
        }
        float inv = 1.0f / s;
#pragma unroll
        for (int k = 0; k < K_; k++) sPh[g][k][m] = __float2half_rn(e[k] * inv);
    }
    __syncthreads();

    // phase 3: warp g handles point q0+g; lane covers channels {2l, 2l+1}
    int g = t >> 5, lane = t & 31;
    int q = q0 + g;
    int b = q >> 12;

    int idxr[K_];
#pragma unroll
    for (int j = 0; j < 5; j++) {
        uint4 v = *(const uint4*)&sIdx[g][j * 4];
        idxr[j * 4]     = (int)v.x; idxr[j * 4 + 1] = (int)v.y;
        idxr[j * 4 + 2] = (int)v.z; idxr[j * 4 + 3] = (int)v.w;
    }

    uint64_t accA[4] = {0, 0, 0, 0};   // {acc0[2j],acc0[2j+1]} channel 2*lane
    uint64_t accB[4] = {0, 0, 0, 0};   // channel 2*lane+1

    const float* ftb = g_ft + (size_t)b * N_ * C_ + 2 * lane;
#pragma unroll
    for (int kb = 0; kb < K_; kb += 4) {
        float2 fv[4];
        uint4  pv[4];
#pragma unroll
        for (int j = 0; j < 4; j++)
            fv[j] = *(const float2*)(ftb + (size_t)idxr[kb + j] * C_);
#pragma unroll
        for (int j = 0; j < 4; j++)
            pv[j] = *(const uint4*)&sPh[g][kb + j][0];
#pragma unroll
        for (int j = 0; j < 4; j++) {
            float2 q0v = __half22float2(*(const __half2*)&pv[j].x);
            float2 q1v = __half22float2(*(const __half2*)&pv[j].y);
            float2 q2v = __half22float2(*(const __half2*)&pv[j].z);
            float2 q3v = __half22float2(*(const __half2*)&pv[j].w);
            uint64_t d0, d1, d2, d3, fxx, fyy;
            PACKF2(d0, q0v.x, q0v.y);
            PACKF2(d1, q1v.x, q1v.y);
            PACKF2(d2, q2v.x, q2v.y);
            PACKF2(d3, q3v.x, q3v.y);
            PACK_BCAST(fxx, fv[j].x);
            PACK_BCAST(fyy, fv[j].y);
            FMA2(accA[0], fxx, d0); FMA2(accA[1], fxx, d1);
            FMA2(accA[2], fxx, d2); FMA2(accA[3], fxx, d3);
            FMA2(accB[0], fyy, d0); FMA2(accB[1], fyy, d1);
            FMA2(accB[2], fyy, d2); FMA2(accB[3], fyy, d3);
        }
    }

    float acc0[M_], acc1[M_];
#pragma unroll
    for (int j = 0; j < 4; j++) {
        UNPACK2(acc0[2 * j], acc0[2 * j + 1], accA[j]);
        UNPACK2(acc1[2 * j], acc1[2 * j + 1], accB[j]);
    }

    // split to bf16 hi/lo; this thread owns 16 consecutive output elems
    uint32_t hp[8], lp[8];
#pragma unroll
    for (int m = 0; m < 4; m++) {
        __nv_bfloat16 h0 = __float2bfloat16(acc0[2 * m]);
        __nv_bfloat16 h1 = __float2bfloat16(acc0[2 * m + 1]);
        __nv_bfloat16 l0 = __float2bfloat16(acc0[2 * m]     - __bfloat162float(h0));
        __nv_bfloat16 l1 = __float2bfloat16(acc0[2 * m + 1] - __bfloat162float(h1));
        hp[m] = ((uint32_t)__bfloat16_as_ushort(h1) << 16) | __bfloat16_as_ushort(h0);
        lp[m] = ((uint32_t)__bfloat16_as_ushort(l1) << 16) | __bfloat16_as_ushort(l0);
        __nv_bfloat16 h2 = __float2bfloat16(acc1[2 * m]);
        __nv_bfloat16 h3 = __float2bfloat16(acc1[2 * m + 1]);
        __nv_bfloat16 l2 = __float2bfloat16(acc1[2 * m]     - __bfloat162float(h2));
        __nv_bfloat16 l3 = __float2bfloat16(acc1[2 * m + 1] - __bfloat162float(h3));
        hp[4 + m] = ((uint32_t)__bfloat16_as_ushort(h3) << 16) | __bfloat16_as_ushort(h2);
        lp[4 + m] = ((uint32_t)__bfloat16_as_ushort(l3) << 16) | __bfloat16_as_ushort(l2);
    }
    size_t o = (size_t)q * CM + (size_t)(2 * lane) * M_;   // 16 elems per thread
    *(uint4*)(&g_agg_hi[o])     = make_uint4(hp[0], hp[1], hp[2], hp[3]);
    *(uint4*)(&g_agg_hi[o + 8]) = make_uint4(hp[4], hp[5], hp[6], hp[7]);
    *(uint4*)(&g_agg_lo[o])     = make_uint4(lp[0], lp[1], lp[2], lp[3]);
    *(uint4*)(&g_agg_lo[o + 8]) = make_uint4(lp[4], lp[5], lp[6], lp[7]);
}

// ----------------------------------------------------------------------------
// Kernel 3: tensor-core GEMM, cp.async 3-stage pipeline.
// D[128 pts][64 oc], 3-term bf16 split, fp32 accum.
// ----------------------------------------------------------------------------
#define KC        32
#define ASTR      40
#define SOS       132
#define BUF_BYTES 30720     // Ah 10240 | Al 10240 | Wh 5120 | Wl 5120
#define OFF_AL    10240
#define OFF_WH    20480
#define OFF_WL    25600
#define NSTAGE    (CM / KC) // 16
#define PSTAGES   3

#define LDSM4(R0, R1, R2, R3, addr)                                        \
    asm volatile("ldmatrix.sync.aligned.m8n8.x4.shared.b16 {%0,%1,%2,%3}, [%4];" \
                 : "=r"(R0), "=r"(R1), "=r"(R2), "=r"(R3) : "r"(addr))

#define MMA(d, a, b0v, b1v)                                                \
    asm volatile("mma.sync.aligned.m16n8k16.row.col.f32.bf16.bf16.f32 "    \
                 "{%0,%1,%2,%3}, {%4,%5,%6,%7}, {%8,%9}, {%0,%1,%2,%3};"   \
                 : "+f"(d[0]), "+f"(d[1]), "+f"(d[2]), "+f"(d[3])          \
                 : "r"(a[0]), "r"(a[1]), "r"(a[2]), "r"(a[3]),             \
                   "r"(b0v), "r"(b1v))

#define CPA(saddr, gptr)                                                   \
    asm volatile("cp.async.cg.shared.global [%0], [%1], 16;"               \
                 :: "r"(saddr), "l"(gptr))

#define ISSUE(s) do {                                                      \
    uint32_t bb_ = smemBase + ((s) % PSTAGES) * BUF_BYTES;                 \
    int ks_ = (s) * KC;                                                    \
    CPA(bb_ + stA,           gA_hi + ks_);                                 \
    CPA(bb_ + stA + 16,      gA_hi + ks_ + 8);                             \
    CPA(bb_ + OFF_AL + stA,      gA_lo + ks_);                             \
    CPA(bb_ + OFF_AL + stA + 16, gA_lo + ks_ + 8);                         \
    if (t < 128) {                                                         \
        CPA(bb_ + OFF_WH + stA,      gW_hi + ks_);                         \
        CPA(bb_ + OFF_WH + stA + 16, gW_hi + ks_ + 8);                     \
        CPA(bb_ + OFF_WL + stA,      gW_lo + ks_);                         \
        CPA(bb_ + OFF_WL + stA + 16, gW_lo + ks_ + 8);                     \
    }                                                                      \
    asm volatile("cp.async.commit_group;");                                \
} while (0)

extern __shared__ unsigned char g_dsm[];

__global__ void __launch_bounds__(256)
gemm_kernel(const float* __restrict__ bias,
            const float* __restrict__ feature,
            float* __restrict__ out) {
    float* sOut = (float*)g_dsm;

    int t  = threadIdx.x;
    int w  = t >> 5, l = t & 31;
    int q0 = blockIdx.x * 128;
    int b  = q0 >> 12;
    int n0 = q0 & (N_ - 1);

    int mw = w & 3, nw = w >> 2;
    int ptb = mw * 32, ocb = nw * 32;

    float acc[2][4][4];
#pragma unroll
    for (int mi = 0; mi < 2; mi++)
#pragma unroll
        for (int nt = 0; nt < 4; nt++)
#pragma unroll
            for (int j = 0; j < 4; j++) acc[mi][nt][j] = 0.0f;

    uint32_t smemBase = (uint32_t)__cvta_generic_to_shared(g_dsm);

    int aRow = ptb + (l & 15);
    int aCol = (l >> 4) * 8;
    int bRow = ocb + ((l >> 4) * 8) + (l & 7);
    int bCol = ((l >> 3) & 1) * 8;

    int pt_g  = t >> 1;
    int seg_g = (t & 1) * 16;
    const __nv_bfloat16* gA_hi = g_agg_hi + (size_t)(q0 + pt_g) * CM + seg_g;
    const __nv_bfloat16* gA_lo = g_agg_lo + (size_t)(q0 + pt_g) * CM + seg_g;
    const __nv_bfloat16* gW_hi = g_w_hi + (size_t)pt_g * CM + seg_g;   // t<128 -> oc 0..63
    const __nv_bfloat16* gW_lo = g_w_lo + (size_t)pt_g * CM + seg_g;
    uint32_t stA = (uint32_t)(pt_g * ASTR + seg_g) * 2;

    ISSUE(0);
    ISSUE(1);

    for (int s = 0; s < NSTAGE; s++) {
        if (s == NSTAGE - 1) asm volatile("cp.async.wait_group 0;");
        else                 asm volatile("cp.async.wait_group 1;");
        __syncthreads();

        uint32_t base = smemBase + (s % PSTAGES) * BUF_BYTES;
#pragma unroll
        for (int step = 0; step < 2; step++) {
            int koff = step * 16;
            uint32_t Ah[2][4], Al[2][4], Bh[2][4], Bl[2][4];
#pragma unroll
            for (int mi = 0; mi < 2; mi++) {
                uint32_t off = (uint32_t)((aRow + mi * 16) * ASTR + aCol + koff) * 2;
                LDSM4(Ah[mi][0], Ah[mi][1], Ah[mi][2], Ah[mi][3], base + off);
                LDSM4(Al[mi][0], Al[mi][1], Al[mi][2], Al[mi][3], base + OFF_AL + off);
            }
#pragma unroll
            for (int ni2 = 0; ni2 < 2; ni2++) {
                uint32_t off = (uint32_t)((bRow + ni2 * 16) * ASTR + bCol + koff) * 2;
                LDSM4(Bh[ni2][0], Bh[ni2][1], Bh[ni2][2], Bh[ni2][3], base + OFF_WH + off);
                LDSM4(Bl[ni2][0], Bl[ni2][1], Bl[ni2][2], Bl[ni2][3], base + OFF_WL + off);
            }
#pragma unroll
            for (int mi = 0; mi < 2; mi++) {
#pragma unroll
                for (int nt = 0; nt < 4; nt++) {
                    int ni2 = nt >> 1, sel = (nt & 1) * 2;
                    MMA(acc[mi][nt], Ah[mi], Bh[ni2][sel], Bh[ni2][sel + 1]);
                    MMA(acc[mi][nt], Ah[mi], Bl[ni2][sel], Bl[ni2][sel + 1]);
                    MMA(acc[mi][nt], Al[mi], Bh[ni2][sel], Bh[ni2][sel + 1]);
                }
            }
        }

        if (s + 2 < NSTAGE) ISSUE(s + 2);   // overwrites buf (s-1)%3: all readers done
    }
    __syncthreads();   // before reusing smem for epilogue

    // epilogue: stage D (pt x oc) into smem as [oc][pt], coalesced store
    int g2 = l >> 2, t4 = l & 3;
#pragma unroll
    for (int mi = 0; mi < 2; mi++) {
#pragma unroll
        for (int nt = 0; nt < 4; nt++) {
            int pt = ptb + mi * 16 + g2;
            int oc = ocb + nt * 8 + 2 * t4;
            sOut[oc * SOS + pt]           = acc[mi][nt][0];
            sOut[(oc + 1) * SOS + pt]     = acc[mi][nt][1];
            sOut[oc * SOS + pt + 8]       = acc[mi][nt][2];
            sOut[(oc + 1) * SOS + pt + 8] = acc[mi][nt][3];
        }
    }
    __syncthreads();

#pragma unroll
    for (int r = 0; r < 8; r++) {
        int oc = w * 8 + r;
        float bs = bias[oc];
        float4 v = *(float4*)&sOut[oc * SOS + l * 4];
        size_t go = ((size_t)(b * OUTC + oc)) * N_ + n0 + l * 4;
        float4 f = *(const float4*)&feature[go];
        v.x += bs; v.x = (v.x > 0.f) ? v.x : NEG_SLOPE * v.x; v.x += f.x;
        v.y += bs; v.y = (v.y > 0.f) ? v.y : NEG_SLOPE * v.y; v.y += f.y;
        v.z += bs; v.z = (v.z > 0.f) ? v.z : NEG_SLOPE * v.z; v.z += f.z;
        v.w += bs; v.w = (v.w > 0.f) ? v.w : NEG_SLOPE * v.w; v.w += f.w;
        *(float4*)&out[go] = v;
    }
}

// ----------------------------------------------------------------------------
extern "C" void kernel_launch(void* const* d_in, const int* in_sizes, int n_in,
                              void* d_out, int out_size) {
    const float* x       = (const float*)d_in[0];
    const float* feature = (const float*)d_in[1];
    const void*  nidx    = d_in[2];
    const float* kern    = (const float*)d_in[3];
    const float* W       = (const float*)d_in[4];
    const float* bias    = (const float*)d_in[5];
    float*       out     = (float*)d_out;

    cudaFuncSetAttribute(gemm_kernel,
                         cudaFuncAttributeMaxDynamicSharedMemorySize,
                         PSTAGES * BUF_BYTES);

    detect_kernel<<<1, 1>>>((const int*)nidx);
    convw_kernel<<<(OUTC * CM) / 256, 256>>>(W);
    transpose_x_kernel<<<dim3(N_ / 256, B_), 256>>>(x);
    dim3 tgrid(N_ / 32, C_ / 32, B_);
    transpose_kernel<<<tgrid, dim3(32, 8)>>>(feature);
    agg_kernel<<<(B_ * N_) / 8, 256>>>(nidx, kern);
    gemm_kernel<<<(B_ * N_) / 128, 256, PSTAGES * BUF_BYTES>>>(bias, feature, out);
}

// round 8
// speedup vs baseline: 1.1259x; 1.1259x over previous
#include <cuda_runtime.h>
#include <cuda_bf16.h>
#include <cuda_fp16.h>
#include <cstdint>

#define B_   8
#define C_   64
#define N_   4096
#define K_   20
#define M_   8
#define OUTC 64
#define CM   512
#define NEG_SLOPE 0.2f

__device__ float           g_ft[B_ * N_ * C_];
__device__ float           g_xt[B_ * N_ * 4];
__device__ __nv_bfloat16   g_agg_hi[(size_t)B_ * N_ * CM];
__device__ __nv_bfloat16   g_agg_lo[(size_t)B_ * N_ * CM];
__device__ __nv_bfloat16   g_w_hi[OUTC * CM];
__device__ __nv_bfloat16   g_w_lo[OUTC * CM];
__device__ int             g_idx_is64;

#define FMA2(d, a, b) \
    asm volatile("fma.rn.f32x2 %0, %1, %2, %0;" : "+l"(d) : "l"(a), "l"(b))
#define PACK_BCAST(dst, v) do { unsigned r_ = __float_as_uint(v); \
    asm("mov.b64 %0, {%1,%2};" : "=l"(dst) : "r"(r_), "r"(r_)); } while (0)
#define PACKF2(dst, lo, hi) do { unsigned lo_ = __float_as_uint(lo), hi_ = __float_as_uint(hi); \
    asm("mov.b64 %0, {%1,%2};" : "=l"(dst) : "r"(lo_), "r"(hi_)); } while (0)
#define UNPACK2(lo, hi, v) do { unsigned lo_, hi_; \
    asm("mov.b64 {%0,%1}, %2;" : "=r"(lo_), "=r"(hi_) : "l"(v)); \
    lo = __uint_as_float(lo_); hi = __uint_as_float(hi_); } while (0)

// ----------------------------------------------------------------------------
// Kernel P: fused prep. blocks [0,512): feature transpose; [512,640): W split;
// [640,768): x transpose; 768: idx dtype detect.
// ----------------------------------------------------------------------------
__global__ void __launch_bounds__(256)
prep_kernel(const float* __restrict__ feature, const float* __restrict__ W,
            const float* __restrict__ x, const int* __restrict__ rawidx) {
    __shared__ float tile[32][133];
    int bid = blockIdx.x;
    int t = threadIdx.x;

    if (bid < 512) {                 // feature (B,C,N) -> g_ft (B,N,C), float4 loads
        int b  = bid >> 6;
        int rem = bid & 63;
        int c0 = (rem >> 5) * 32;
        int n0 = (rem & 31) * 128;
        int cy = t >> 5, nx = (t & 31) * 4;
#pragma unroll
        for (int p = 0; p < 4; p++) {
            int c = c0 + cy + p * 8;
            float4 v = *(const float4*)&feature[((size_t)b * C_ + c) * N_ + n0 + nx];
            tile[cy + p * 8][nx]     = v.x;
            tile[cy + p * 8][nx + 1] = v.y;
            tile[cy + p * 8][nx + 2] = v.z;
            tile[cy + p * 8][nx + 3] = v.w;
        }
        __syncthreads();
        int c4 = (t & 7) * 4;
#pragma unroll
        for (int it = 0; it < 4; it++) {
            int n = (t >> 3) + it * 32;
            float4 v = make_float4(tile[c4][n], tile[c4 + 1][n],
                                   tile[c4 + 2][n], tile[c4 + 3][n]);
            *(float4*)&g_ft[((size_t)b * N_ + n0 + n) * C_ + c0 + c4] = v;
        }
    } else if (bid < 640) {          // conv_w bf16 hi/lo split
        int i = (bid - 512) * 256 + t;
        float w = W[i];
        __nv_bfloat16 h = __float2bfloat16(w);
        g_w_hi[i] = h;
        g_w_lo[i] = __float2bfloat16(w - __bfloat162float(h));
    } else if (bid < 768) {          // x (B,3,N) -> g_xt (B,N,4)
        int r = bid - 640;
        int b = r >> 4;
        int n = (r & 15) * 256 + t;
        const float* xb = x + (size_t)b * 3 * N_;
        *(float4*)&g_xt[((size_t)b * N_ + n) * 4] =
            make_float4(xb[n], xb[N_ + n], xb[2 * N_ + n], 0.0f);
    } else {                         // detect idx dtype
        if (t == 0) {
            int all0 = 1;
#pragma unroll
            for (int j = 1; j < 64; j += 2)
                if (rawidx[j] != 0) all0 = 0;
            g_idx_is64 = all0;
        }
    }
}

// ----------------------------------------------------------------------------
// Kernel 2: per-point perm + softmax + agg -> bf16 hi/lo (R6, proven)
// ----------------------------------------------------------------------------
__global__ void __launch_bounds__(256)
agg_kernel(const void* __restrict__ nidx, const float* __restrict__ kern) {
    __shared__ __align__(16) int    sIdx[8][K_];
    __shared__ __align__(16) float  sP[8][K_][M_];
    __shared__ __align__(16) __half sPh[8][K_][M_];

    int t  = threadIdx.x;
    int q0 = blockIdx.x * 8;
    int is64 = g_idx_is64;

    if (t < 8 * K_) {
        int g = t / K_, k = t % K_;
        int q = q0 + g;
        int b = q >> 12;
        size_t pos = (size_t)q * K_ + k;
        int i, i0;
        if (is64) {
            i  = (int)((const long long*)nidx)[pos];
            i0 = (int)((const long long*)nidx)[(size_t)q * K_];
        } else {
            i  = ((const int*)nidx)[pos];
            i0 = ((const int*)nidx)[(size_t)q * K_];
        }
        i  &= (N_ - 1);
        i0 &= (N_ - 1);
        sIdx[g][k] = i;
        float4 xv  = *(const float4*)&g_xt[((size_t)b * N_ + i) * 4];
        float4 x0v = *(const float4*)&g_xt[((size_t)b * N_ + i0) * 4];
        float x0 = xv.x - x0v.x, x1 = xv.y - x0v.y, x2 = xv.z - x0v.z;
#pragma unroll
        for (int m = 0; m < M_; m++) {
            float v = x0 * kern[m] + x1 * kern[M_ + m] + x2 * kern[2 * M_ + m];
            if (k == 0 && m == 0) v += 1.0f;
            sP[g][k][m] = v;
        }
    }
    __syncthreads();

    if (t < 8 * M_) {
        int g = t >> 3, m = t & 7;
        float e[K_];
        float mx = -1e30f;
#pragma unroll
        for (int k = 0; k < K_; k++) mx = fmaxf(mx, sP[g][k][m]);
        float s = 0.0f;
#pragma unroll
        for (int k = 0; k < K_; k++) { float ee = __expf(sP[g][k][m] - mx); e[k] = ee; s += ee; }
        float inv = 1.0f / s;
#pragma unroll
        for (int k = 0; k < K_; k++) sPh[g][k][m] = __float2half_rn(e[k] * inv);
    }
    __syncthreads();

    int g = t >> 5, lane = t & 31;
    int q = q0 + g;
    int b = q >> 12;

    int idxr[K_];
#pragma unroll
    for (int j = 0; j < 5; j++) {
        uint4 v = *(const uint4*)&sIdx[g][j * 4];
        idxr[j * 4]     = (int)v.x; idxr[j * 4 + 1] = (int)v.y;
        idxr[j * 4 + 2] = (int)v.z; idxr[j * 4 + 3] = (int)v.w;
    }

    uint64_t accA[4] = {0, 0, 0, 0};
    uint64_t accB[4] = {0, 0, 0, 0};

    const float* ftb = g_ft + (size_t)b * N_ * C_ + 2 * lane;
#pragma unroll
    for (int kb = 0; kb < K_; kb += 4) {
        float2 fv[4];
        uint4  pv[4];
#pragma unroll
        for (int j = 0; j < 4; j++)
            fv[j] = *(const float2*)(ftb + (size_t)idxr[kb + j] * C_);
#pragma unroll
        for (int j = 0; j < 4; j++)
            pv[j] = *(const uint4*)&sPh[g][kb + j][0];
#pragma unroll
        for (int j = 0; j < 4; j++) {
            float2 q0v = __half22float2(*(const __half2*)&pv[j].x);
            float2 q1v = __half22float2(*(const __half2*)&pv[j].y);
            float2 q2v = __half22float2(*(const __half2*)&pv[j].z);
            float2 q3v = __half22float2(*(const __half2*)&pv[j].w);
            uint64_t d0, d1, d2, d3, fxx, fyy;
            PACKF2(d0, q0v.x, q0v.y);
            PACKF2(d1, q1v.x, q1v.y);
            PACKF2(d2, q2v.x, q2v.y);
            PACKF2(d3, q3v.x, q3v.y);
            PACK_BCAST(fxx, fv[j].x);
            PACK_BCAST(fyy, fv[j].y);
            FMA2(accA[0], fxx, d0); FMA2(accA[1], fxx, d1);
            FMA2(accA[2], fxx, d2); FMA2(accA[3], fxx, d3);
            FMA2(accB[0], fyy, d0); FMA2(accB[1], fyy, d1);
            FMA2(accB[2], fyy, d2); FMA2(accB[3], fyy, d3);
        }
    }

    float acc0[M_], acc1[M_];
#pragma unroll
    for (int j = 0; j < 4; j++) {
        UNPACK2(acc0[2 * j], acc0[2 * j + 1], accA[j]);
        UNPACK2(acc1[2 * j], acc1[2 * j + 1], accB[j]);
    }

    uint32_t hp[8], lp[8];
#pragma unroll
    for (int m = 0; m < 4; m++) {
        __nv_bfloat16 h0 = __float2bfloat16(acc0[2 * m]);
        __nv_bfloat16 h1 = __float2bfloat16(acc0[2 * m + 1]);
        __nv_bfloat16 l0 = __float2bfloat16(acc0[2 * m]     - __bfloat162float(h0));
        __nv_bfloat16 l1 = __float2bfloat16(acc0[2 * m + 1] - __bfloat162float(h1));
        hp[m] = ((uint32_t)__bfloat16_as_ushort(h1) << 16) | __bfloat16_as_ushort(h0);
        lp[m] = ((uint32_t)__bfloat16_as_ushort(l1) << 16) | __bfloat16_as_ushort(l0);
        __nv_bfloat16 h2 = __float2bfloat16(acc1[2 * m]);
        __nv_bfloat16 h3 = __float2bfloat16(acc1[2 * m + 1]);
        __nv_bfloat16 l2 = __float2bfloat16(acc1[2 * m]     - __bfloat162float(h2));
        __nv_bfloat16 l3 = __float2bfloat16(acc1[2 * m + 1] - __bfloat162float(h3));
        hp[4 + m] = ((uint32_t)__bfloat16_as_ushort(h3) << 16) | __bfloat16_as_ushort(h2);
        lp[4 + m] = ((uint32_t)__bfloat16_as_ushort(l3) << 16) | __bfloat16_as_ushort(l2);
    }
    size_t o = (size_t)q * CM + (size_t)(2 * lane) * M_;
    *(uint4*)(&g_agg_hi[o])     = make_uint4(hp[0], hp[1], hp[2], hp[3]);
    *(uint4*)(&g_agg_hi[o + 8]) = make_uint4(hp[4], hp[5], hp[6], hp[7]);
    *(uint4*)(&g_agg_lo[o])     = make_uint4(lp[0], lp[1], lp[2], lp[3]);
    *(uint4*)(&g_agg_lo[o + 8]) = make_uint4(lp[4], lp[5], lp[6], lp[7]);
}

// ----------------------------------------------------------------------------
// Kernel 3: tensor-core GEMM, cp.async 3-stage pipeline (R6, proven)
// ----------------------------------------------------------------------------
#define KC        32
#define ASTR      40
#define SOS       132
#define BUF_BYTES 30720
#define OFF_AL    10240
#define OFF_WH    20480
#define OFF_WL    25600
#define NSTAGE    (CM / KC)
#define PSTAGES   3

#define LDSM4(R0, R1, R2, R3, addr)                                        \
    asm volatile("ldmatrix.sync.aligned.m8n8.x4.shared.b16 {%0,%1,%2,%3}, [%4];" \
                 : "=r"(R0), "=r"(R1), "=r"(R2), "=r"(R3) : "r"(addr))

#define MMA(d, a, b0v, b1v)                                                \
    asm volatile("mma.sync.aligned.m16n8k16.row.col.f32.bf16.bf16.f32 "    \
                 "{%0,%1,%2,%3}, {%4,%5,%6,%7}, {%8,%9}, {%0,%1,%2,%3};"   \
                 : "+f"(d[0]), "+f"(d[1]), "+f"(d[2]), "+f"(d[3])          \
                 : "r"(a[0]), "r"(a[1]), "r"(a[2]), "r"(a[3]),             \
                   "r"(b0v), "r"(b1v))

#define CPA(saddr, gptr)                                                   \
    asm volatile("cp.async.cg.shared.global [%0], [%1], 16;"               \
                 :: "r"(saddr), "l"(gptr))

#define ISSUE(s) do {                                                      \
    uint32_t bb_ = smemBase + ((s) % PSTAGES) * BUF_BYTES;                 \
    int ks_ = (s) * KC;                                                    \
    CPA(bb_ + stA,           gA_hi + ks_);                                 \
    CPA(bb_ + stA + 16,      gA_hi + ks_ + 8);                             \
    CPA(bb_ + OFF_AL + stA,      gA_lo + ks_);                             \
    CPA(bb_ + OFF_AL + stA + 16, gA_lo + ks_ + 8);                         \
    if (t < 128) {                                                         \
        CPA(bb_ + OFF_WH + stA,      gW_hi + ks_);                         \
        CPA(bb_ + OFF_WH + stA + 16, gW_hi + ks_ + 8);                     \
        CPA(bb_ + OFF_WL + stA,      gW_lo + ks_);                         \
        CPA(bb_ + OFF_WL + stA + 16, gW_lo + ks_ + 8);                     \
    }                                                                      \
    asm volatile("cp.async.commit_group;");                                \
} while (0)

extern __shared__ unsigned char g_dsm[];

__global__ void __launch_bounds__(256)
gemm_kernel(const float* __restrict__ bias,
            const float* __restrict__ feature,
            float* __restrict__ out) {
    float* sOut = (float*)g_dsm;

    int t  = threadIdx.x;
    int w  = t >> 5, l = t & 31;
    int q0 = blockIdx.x * 128;
    int b  = q0 >> 12;
    int n0 = q0 & (N_ - 1);

    int mw = w & 3, nw = w >> 2;
    int ptb = mw * 32, ocb = nw * 32;

    float acc[2][4][4];
#pragma unroll
    for (int mi = 0; mi < 2; mi++)
#pragma unroll
        for (int nt = 0; nt < 4; nt++)
#pragma unroll
            for (int j = 0; j < 4; j++) acc[mi][nt][j] = 0.0f;

    uint32_t smemBase = (uint32_t)__cvta_generic_to_shared(g_dsm);

    int aRow = ptb + (l & 15);
    int aCol = (l >> 4) * 8;
    int bRow = ocb + ((l >> 4) * 8) + (l & 7);
    int bCol = ((l >> 3) & 1) * 8;

    int pt_g  = t >> 1;
    int seg_g = (t & 1) * 16;
    const __nv_bfloat16* gA_hi = g_agg_hi + (size_t)(q0 + pt_g) * CM + seg_g;
    const __nv_bfloat16* gA_lo = g_agg_lo + (size_t)(q0 + pt_g) * CM + seg_g;
    const __nv_bfloat16* gW_hi = g_w_hi + (size_t)pt_g * CM + seg_g;
    const __nv_bfloat16* gW_lo = g_w_lo + (size_t)pt_g * CM + seg_g;
    uint32_t stA = (uint32_t)(pt_g * ASTR + seg_g) * 2;

    ISSUE(0);
    ISSUE(1);

    for (int s = 0; s < NSTAGE; s++) {
        if (s == NSTAGE - 1) asm volatile("cp.async.wait_group 0;");
        else                 asm volatile("cp.async.wait_group 1;");
        __syncthreads();

        uint32_t base = smemBase + (s % PSTAGES) * BUF_BYTES;
#pragma unroll
        for (int step = 0; step < 2; step++) {
            int koff = step * 16;
            uint32_t Ah[2][4], Al[2][4], Bh[2][4], Bl[2][4];
#pragma unroll
            for (int mi = 0; mi < 2; mi++) {
                uint32_t off = (uint32_t)((aRow + mi * 16) * ASTR + aCol + koff) * 2;
                LDSM4(Ah[mi][0], Ah[mi][1], Ah[mi][2], Ah[mi][3], base + off);
                LDSM4(Al[mi][0], Al[mi][1], Al[mi][2], Al[mi][3], base + OFF_AL + off);
            }
#pragma unroll
            for (int ni2 = 0; ni2 < 2; ni2++) {
                uint32_t off = (uint32_t)((bRow + ni2 * 16) * ASTR + bCol + koff) * 2;
                LDSM4(Bh[ni2][0], Bh[ni2][1], Bh[ni2][2], Bh[ni2][3], base + OFF_WH + off);
                LDSM4(Bl[ni2][0], Bl[ni2][1], Bl[ni2][2], Bl[ni2][3], base + OFF_WL + off);
            }
#pragma unroll
            for (int mi = 0; mi < 2; mi++) {
#pragma unroll
                for (int nt = 0; nt < 4; nt++) {
                    int ni2 = nt >> 1, sel = (nt & 1) * 2;
                    MMA(acc[mi][nt], Ah[mi], Bh[ni2][sel], Bh[ni2][sel + 1]);
                    MMA(acc[mi][nt], Ah[mi], Bl[ni2][sel], Bl[ni2][sel + 1]);
                    MMA(acc[mi][nt], Al[mi], Bh[ni2][sel], Bh[ni2][sel + 1]);
                }
            }
        }

        if (s + 2 < NSTAGE) ISSUE(s + 2);
    }
    __syncthreads();

    int g2 = l >> 2, t4 = l & 3;
#pragma unroll
    for (int mi = 0; mi < 2; mi++) {
#pragma unroll
        for (int nt = 0; nt < 4; nt++) {
            int pt = ptb + mi * 16 + g2;
            int oc = ocb + nt * 8 + 2 * t4;
            sOut[oc * SOS + pt]           = acc[mi][nt][0];
            sOut[(oc + 1) * SOS + pt]     = acc[mi][nt][1];
            sOut[oc * SOS + pt + 8]       = acc[mi][nt][2];
            sOut[(oc + 1) * SOS + pt + 8] = acc[mi][nt][3];
        }
    }
    __syncthreads();

#pragma unroll
    for (int r = 0; r < 8; r++) {
        int oc = w * 8 + r;
        float bs = bias[oc];
        float4 v = *(float4*)&sOut[oc * SOS + l * 4];
        size_t go = ((size_t)(b * OUTC + oc)) * N_ + n0 + l * 4;
        float4 f = *(const float4*)&feature[go];
        v.x += bs; v.x = (v.x > 0.f) ? v.x : NEG_SLOPE * v.x; v.x += f.x;
        v.y += bs; v.y = (v.y > 0.f) ? v.y : NEG_SLOPE * v.y; v.y += f.y;
        v.z += bs; v.z = (v.z > 0.f) ? v.z : NEG_SLOPE * v.z; v.z += f.z;
        v.w += bs; v.w = (v.w > 0.f) ? v.w : NEG_SLOPE * v.w; v.w += f.w;
        *(float4*)&out[go] = v;
    }
}

// ----------------------------------------------------------------------------
extern "C" void kernel_launch(void* const* d_in, const int* in_sizes, int n_in,
                              void* d_out, int out_size) {
    const float* x       = (const float*)d_in[0];
    const float* feature = (const float*)d_in[1];
    const void*  nidx    = d_in[2];
    const float* kern    = (const float*)d_in[3];
    const float* W       = (const float*)d_in[4];
    const float* bias    = (const float*)d_in[5];
    float*       out     = (float*)d_out;

    cudaFuncSetAttribute(gemm_kernel,
                         cudaFuncAttributeMaxDynamicSharedMemorySize,
                         PSTAGES * BUF_BYTES);

    prep_kernel<<<769, 256>>>(feature, W, x, (const int*)nidx);
    agg_kernel<<<(B_ * N_) / 8, 256>>>(nidx, kern);
    gemm_kernel<<<(B_ * N_) / 128, 256, PSTAGES * BUF_BYTES>>>(bias, feature, out);
}